// round 2
// baseline (speedup 1.0000x reference)
#include <cuda_runtime.h>
#include <math.h>

// SpritesAndTexturesCoordinateDecoder — fused fp32 (f32x2-packed) decoder.
//
// Pipeline per pixel:
//   emb(32) -> L0(32->128,lrelu) -> L1(128->128) -> L2(128->128)
//   shape = h . wsh + bsh, modulated by radius
//   T0(128->128, +tex-bias) -> T1(128->128) -> texture = t @ wt2^T(3)
// shape_cond / texture_cond slices are folded into per-batch biases by a
// tiny precompute kernel.

typedef unsigned long long ull;

#define PB 128          // pixels per CTA
#define NPAIR 64        // pixel pairs per CTA
#define HSTRIDE 129     // ull (float2) stride per pair-row in smem

// ---------------- device scratch (precomputed, deterministic) ----------------
__device__ __align__(16) float g_W0 [32 * 128];    // [k][j], scaled
__device__ __align__(16) float g_W1 [128 * 128];
__device__ __align__(16) float g_W2 [128 * 128];
__device__ __align__(16) float g_Wt0[128 * 128];
__device__ __align__(16) float g_Wt1[128 * 128];
__device__ __align__(16) float g_Wt2[128 * 4];     // [k][c], c<3 real
__device__ __align__(16) float g_wsh[128];
__device__ __align__(16) float g_b0 [8 * 128];     // per-batch effective bias (layer0)
__device__ __align__(16) float g_bt0[8 * 128];     // per-batch effective bias (t0)

// ---------------- f32x2 helpers ----------------
__device__ __forceinline__ ull pack2(float x, float y) {
    ull r; asm("mov.b64 %0, {%1,%2};" : "=l"(r) : "f"(x), "f"(y)); return r;
}
__device__ __forceinline__ ull dup2(float x) {
    ull r; asm("mov.b64 %0, {%1,%1};" : "=l"(r) : "f"(x)); return r;
}
__device__ __forceinline__ float2 unpack2(ull v) {
    float2 f; asm("mov.b64 {%0,%1}, %2;" : "=f"(f.x), "=f"(f.y) : "l"(v)); return f;
}
__device__ __forceinline__ void ffma2(ull& d, ull a, ull b) {
    asm("fma.rn.f32x2 %0, %1, %2, %0;" : "+l"(d) : "l"(a), "l"(b));
}

__device__ __forceinline__ float lrelu_s2(float v) {
    // leaky_relu(v, 0.2) * sqrt(2)
    return v > 0.f ? v * 1.4142135623730951f : v * 0.28284271247461907f;
}

// Precise sincos immune to --use_fast_math (args up to ~±80 rad).
__device__ __forceinline__ void my_sincos(float x, float* sp, float* cp) {
    float k = rintf(x * 0.63661977236758134f);          // x * 2/pi
    int   q = (int)k;
    // pi/2 = C1 + C2 (Cody-Waite split)
    float r = fmaf(k, -1.5707963705062866f, x);
    r       = fmaf(k,  4.3711390001862456e-8f, r);
    float r2 = r * r;
    // sin(r) = r + r^3 * P(r^2)
    float p  = fmaf(r2, fmaf(r2, -1.9841271e-4f, 8.3333310e-3f), -1.6666667e-1f);
    float s  = p * r2;                                   // r2 * P
    s = fmaf(s, r, r);                                   // r + r^3 * P
    // cos(r) = 1 - r^2/2 + r^4 * Q(r^2)
    float qq2 = fmaf(r2, fmaf(r2, 2.4801587e-5f, -1.3888889e-3f), 4.1666668e-2f);
    float c  = qq2 * r2;                                 // r2 * Q
    c = fmaf(c, r2, fmaf(r2, -0.5f, 1.f));               // 1 - r2/2 + r4 * Q
    int   qm = q & 3;
    float sv = (qm & 1) ? c : s;
    float cv = (qm & 1) ? s : c;
    if (qm == 1 || qm == 2) cv = -cv;
    if (qm == 2 || qm == 3) sv = -sv;
    *sp = sv; *cp = cv;
}

// ---------------- precompute: scale/transpose weights, fold cond into bias ----
__global__ void prep_kernel(
    const float* __restrict__ ws0, const float* __restrict__ bs0,
    const float* __restrict__ sc,
    const float* __restrict__ ws1, const float* __restrict__ ws2,
    const float* __restrict__ wsh,
    const float* __restrict__ wt0, const float* __restrict__ bt0,
    const float* __restrict__ tc,
    const float* __restrict__ wt1, const float* __restrict__ wt2,
    int B)
{
    const float s0  = 1.f / sqrtf(96.f);
    const float s1  = 1.f / sqrtf(128.f);
    const float st0 = 1.f / sqrtf(192.f);
    int nth = blockDim.x * gridDim.x;
    int tid = blockIdx.x * blockDim.x + threadIdx.x;

    for (int idx = tid; idx < 32 * 128; idx += nth) {
        int k = idx >> 7, j = idx & 127;
        g_W0[k * 128 + j] = ws0[j * 96 + k] * s0;
    }
    for (int idx = tid; idx < 128 * 128; idx += nth) {
        int k = idx >> 7, j = idx & 127;
        g_W1 [k * 128 + j] = ws1[j * 128 + k] * s1;
        g_W2 [k * 128 + j] = ws2[j * 128 + k] * s1;
        g_Wt0[k * 128 + j] = wt0[j * 192 + k] * st0;
        g_Wt1[k * 128 + j] = wt1[j * 128 + k] * s1;
    }
    for (int idx = tid; idx < 128; idx += nth) g_wsh[idx] = wsh[idx] * s1;
    for (int idx = tid; idx < 128 * 4; idx += nth) {
        int k = idx >> 2, c = idx & 3;
        g_Wt2[k * 4 + c] = (c < 3) ? wt2[c * 128 + k] * s1 : 0.f;
    }
    for (int idx = tid; idx < B * 128 && idx < 8 * 128; idx += nth) {
        int b = idx >> 7, j = idx & 127;
        float a = 0.f, t = 0.f;
        for (int m = 0; m < 64; m++) {
            a += sc[b * 64 + m] * ws0[j * 96 + 32 + m];
            t += tc[b * 64 + m] * wt0[j * 192 + 128 + m];
        }
        g_b0 [b * 128 + j] = bs0[j] + a * s0;
        g_bt0[b * 128 + j] = bt0[j] + t * st0;
    }
}

// ---------------- fused layer: [128px x 128out x K] GEMM + lrelu, in-place smem
template <int K>
__device__ __forceinline__ void layer_fn(ull* h2, const float* __restrict__ W,
                                         const float* __restrict__ bias,
                                         int tx, int ty)
{
    ull acc[4][8];
    {
        const float4 b0 = *(const float4*)&bias[tx * 8];
        const float4 b1 = *(const float4*)&bias[tx * 8 + 4];
        ull bi[8] = { dup2(b0.x), dup2(b0.y), dup2(b0.z), dup2(b0.w),
                      dup2(b1.x), dup2(b1.y), dup2(b1.z), dup2(b1.w) };
#pragma unroll
        for (int i = 0; i < 4; i++)
#pragma unroll
            for (int j = 0; j < 8; j++) acc[i][j] = bi[j];
    }
    const ull* r0 = h2 + (ty * 4 + 0) * HSTRIDE;
    const ull* r1 = h2 + (ty * 4 + 1) * HSTRIDE;
    const ull* r2 = h2 + (ty * 4 + 2) * HSTRIDE;
    const ull* r3 = h2 + (ty * 4 + 3) * HSTRIDE;

#pragma unroll 4
    for (int k = 0; k < K; k++) {
        ull h0 = r0[k], h1 = r1[k], h2v = r2[k], h3 = r3[k];
        const float4 wa = *(const float4*)&W[k * 128 + tx * 8];
        const float4 wb = *(const float4*)&W[k * 128 + tx * 8 + 4];
        ull w[8] = { dup2(wa.x), dup2(wa.y), dup2(wa.z), dup2(wa.w),
                     dup2(wb.x), dup2(wb.y), dup2(wb.z), dup2(wb.w) };
#pragma unroll
        for (int j = 0; j < 8; j++) {
            ffma2(acc[0][j], h0,  w[j]);
            ffma2(acc[1][j], h1,  w[j]);
            ffma2(acc[2][j], h2v, w[j]);
            ffma2(acc[3][j], h3,  w[j]);
        }
    }
    __syncthreads();   // all reads of h2 complete before anyone overwrites
#pragma unroll
    for (int i = 0; i < 4; i++) {
        float2* orow = (float2*)(h2 + (ty * 4 + i) * HSTRIDE);
#pragma unroll
        for (int j = 0; j < 8; j++) {
            float2 v = unpack2(acc[i][j]);
            v.x = lrelu_s2(v.x);
            v.y = lrelu_s2(v.y);
            orow[tx * 8 + j] = v;
        }
    }
    __syncthreads();
}

// ---------------- main fused kernel ----------------
extern __shared__ ull s_h2[];   // NPAIR * HSTRIDE ull = 66048 B

__global__ __launch_bounds__(256, 2)
void decoder_kernel(const float* __restrict__ coords,
                    const float* __restrict__ bs1, const float* __restrict__ bs2,
                    const float* __restrict__ bsh, const float* __restrict__ bt1,
                    const float* __restrict__ bt2,
                    float* __restrict__ out, int HW, int BHW)
{
    ull* h2 = s_h2;
    int tid = threadIdx.x;
    int tx = tid & 15, ty = tid >> 4;
    int base = blockIdx.x * PB;
    int batch = base / HW;

    // ---- sinusoidal embedding (channels: [sin cx f, sin cy f, cos cx f, cos cy f] per freq)
    if (tid < PB) {
        int pix = base + tid;
        float cx = coords[2 * pix]     * 0.1f;
        float cy = coords[2 * pix + 1] * 0.1f;
        float* row = (float*)(h2 + (tid >> 1) * HSTRIDE) + (tid & 1);
        float fx = cx, fy = cy;
#pragma unroll
        for (int s = 0; s < 8; s++) {
            float sx, cxv, sy, cyv;
            my_sincos(fx, &sx, &cxv);
            my_sincos(fy, &sy, &cyv);
            row[(4 * s + 0) * 2] = sx;
            row[(4 * s + 1) * 2] = sy;
            row[(4 * s + 2) * 2] = cxv;
            row[(4 * s + 3) * 2] = cyv;
            fx += fx; fy += fy;
        }
    }
    __syncthreads();

    layer_fn<32> (h2, g_W0, &g_b0[batch * 128], tx, ty);
    layer_fn<128>(h2, g_W1, bs1, tx, ty);
    layer_fn<128>(h2, g_W2, bs2, tx, ty);

    // ---- shape head + radius modulation (reads h2 before T0 overwrites it)
    if (tid < NPAIR) {
        const ull* hr = h2 + tid * HSTRIDE;
        ull acc = pack2(0.f, 0.f);
#pragma unroll 4
        for (int k = 0; k < 128; k++) ffma2(acc, hr[k], dup2(g_wsh[k]));
        float2 s = unpack2(acc);
        float b = bsh[0];
        int p0 = base + 2 * tid;
        float c0x = coords[2 * p0],     c0y = coords[2 * p0 + 1];
        float c1x = coords[2 * p0 + 2], c1y = coords[2 * p0 + 3];
        float r0v = sqrtf(c0x * c0x + c0y * c0y);
        float r1v = sqrtf(c1x * c1x + c1y * c1y);
        float m0 = 1.f - tanhf(fmaxf(r0v - 1.f, 0.f));
        float m1 = 1.f - tanhf(fmaxf(r1v - 1.f, 0.f));
        out[p0]     = (s.x + b) * m0;
        out[p0 + 1] = (s.y + b) * m1;
    }

    layer_fn<128>(h2, g_Wt0, &g_bt0[batch * 128], tx, ty);
    layer_fn<128>(h2, g_Wt1, bt1, tx, ty);

    // ---- texture head (3 outputs)
    if (tid < NPAIR) {
        const ull* hr = h2 + tid * HSTRIDE;
        ull a0 = pack2(0.f, 0.f), a1 = a0, a2 = a0;
#pragma unroll 4
        for (int k = 0; k < 128; k++) {
            ull hv = hr[k];
            const float4 w = *(const float4*)&g_Wt2[k * 4];
            ffma2(a0, hv, dup2(w.x));
            ffma2(a1, hv, dup2(w.y));
            ffma2(a2, hv, dup2(w.z));
        }
        float2 t0 = unpack2(a0), t1 = unpack2(a1), t2 = unpack2(a2);
        int p0 = base + 2 * tid;
        float* tp = out + BHW;
        float bb0 = bt2[0], bb1 = bt2[1], bb2 = bt2[2];
        tp[(ull)p0 * 3 + 0] = t0.x + bb0;
        tp[(ull)p0 * 3 + 1] = t1.x + bb1;
        tp[(ull)p0 * 3 + 2] = t2.x + bb2;
        tp[(ull)p0 * 3 + 3] = t0.y + bb0;
        tp[(ull)p0 * 3 + 4] = t1.y + bb1;
        tp[(ull)p0 * 3 + 5] = t2.y + bb2;
    }
}

// ---------------- launch ----------------
extern "C" void kernel_launch(void* const* d_in, const int* in_sizes, int n_in,
                              void* d_out, int out_size)
{
    const float* coords = (const float*)d_in[0];
    const float* sc     = (const float*)d_in[1];
    const float* tc     = (const float*)d_in[2];
    const float* ws0 = (const float*)d_in[3];  const float* bs0 = (const float*)d_in[4];
    const float* ws1 = (const float*)d_in[5];  const float* bs1 = (const float*)d_in[6];
    const float* ws2 = (const float*)d_in[7];  const float* bs2 = (const float*)d_in[8];
    const float* wsh = (const float*)d_in[9];  const float* bsh = (const float*)d_in[10];
    const float* wt0 = (const float*)d_in[11]; const float* bt0 = (const float*)d_in[12];
    const float* wt1 = (const float*)d_in[13]; const float* bt1 = (const float*)d_in[14];
    const float* wt2 = (const float*)d_in[15]; const float* bt2 = (const float*)d_in[16];
    float* out = (float*)d_out;

    int B   = in_sizes[1] / 64;
    int BHW = in_sizes[0] / 2;
    int HW  = BHW / B;

    prep_kernel<<<32, 256>>>(ws0, bs0, sc, ws1, ws2, wsh, wt0, bt0, tc, wt1, wt2, B);

    int smem = NPAIR * HSTRIDE * (int)sizeof(ull);
    cudaFuncSetAttribute(decoder_kernel, cudaFuncAttributeMaxDynamicSharedMemorySize, smem);
    decoder_kernel<<<BHW / PB, 256, smem>>>(coords, bs1, bs2, bsh, bt1, bt2, out, HW, BHW);
}